// round 13
// baseline (speedup 1.0000x reference)
#include <cuda_runtime.h>
#include <math.h>

#define NCOL 22
#define NEMB 12
#define D    64
#define B    2048
#define NPAIR 253           // 22 diag + 231 upper pairs
#define NE2  (NEMB*NEMB)    // 144
#define SZ   (NCOL*NCOL*2*D)

// ---------------- scratch (device globals; no allocation allowed) ------------
__device__ float  g_colsq[NCOL];               // per-col sum over batch
__device__ float2 g_S[NPAIR * NE2];            // pairwise lookup table, 291 KB

// p -> (i,j) upper-triangular-incl-diag enumeration
__device__ __forceinline__ void pair_ij(int p, int& i, int& j) {
    int ii = 0, rem = p;
    while (rem >= NCOL - ii) { rem -= NCOL - ii; ii++; }
    i = ii; j = ii + rem;
}

// fast tanh: EX2 + RCP, safe for any x (measured rel_err ~2.7e-6 end-to-end)
__device__ __forceinline__ float tanh_fast(float x) {
    float e = __expf(-2.0f * fabsf(x));
    float t = __fdividef(1.0f - e, 1.0f + e);
    return copysignf(t, x);
}

// ---------------- k_S: self-sufficient blocks, no precompute kernel ----------
// blocks 0..252   : pair tabulation (computes own T tiles; diag also own L)
// blocks 253..274 : colsq gather (computes own n2 from tables)
__global__ void __launch_bounds__(384)
k_S(const float* __restrict__ tables,
    const float* __restrict__ w1, const float* __restrict__ b1,
    const float* __restrict__ w2, const float* __restrict__ b2,
    const float* __restrict__ Wops, const float* __restrict__ Wcat,
    const float* __restrict__ aw, const int* __restrict__ features) {
    int bid = blockIdx.x, t = threadIdx.x;

    if (bid >= NPAIR) {
        // ---- colsq[i] = sum_b n2[i, feat[i,b]], n2 computed inline ----
        int i = bid - NPAIR;
        __shared__ float s_part[24];
        __shared__ float s_n2c[NEMB];
        __shared__ float s_w[12];
        int w = t >> 5, lane = t & 31;
        for (int c = w; c < 24; c += 12) {             // 24 half-row chunks
            float x = tables[i * NEMB * D + c * 32 + lane];
            float sq = x * x;
#pragma unroll
            for (int o = 16; o; o >>= 1) sq += __shfl_xor_sync(0xffffffffu, sq, o);
            if (lane == 0) s_part[c] = sq;
        }
        __syncthreads();
        if (t < NEMB) s_n2c[t] = s_part[2 * t] + s_part[2 * t + 1];
        __syncthreads();
        float sum = 0.f;
        for (int b = t; b < B; b += 384)
            sum += s_n2c[features[i * B + b]];
#pragma unroll
        for (int o = 16; o; o >>= 1) sum += __shfl_xor_sync(0xffffffffu, sum, o);
        if (lane == 0) s_w[w] = sum;
        __syncthreads();
        if (t == 0) {
            float v = 0.f;
            for (int k = 0; k < 12; k++) v += s_w[k];
            g_colsq[i] = v;
        }
        return;
    }

    int p = bid;
    int i, j; pair_ij(p, i, j);
    bool diag = (i == j);

    __shared__ float  sTi[NEMB][D + 1];  // +1 pad: distinct banks across e
    __shared__ float  sTj[NEMB][D + 1];
    __shared__ float  sWraw[12][D];      // 12 raw weight rows
    __shared__ float4 sW[D];             // {wq0,wq1,wd0,wd1}
    __shared__ float  sL[2 * D];
    __shared__ float4 s_Lred[3][128];

    // ---- Stage A0: T tiles inline (2 elements per column per thread) ----
    {
        float W1[8], B1[8], W2v[8];
#pragma unroll
        for (int h = 0; h < 8; h++) { W1[h] = w1[h]; B1[h] = b1[h]; W2v[h] = w2[h]; }
        float B2v = b2[0];
#pragma unroll
        for (int r = 0; r < 2; r++) {
            int n = t + r * 384;                       // < 768
            float xi = tables[i * NEMB * D + n];
            float xj = tables[j * NEMB * D + n];
            float fi = B2v, fj = B2v;
#pragma unroll
            for (int h = 0; h < 8; h++) {
                fi += W2v[h] * tanh_fast(xi * W1[h] + B1[h]);
                fj += W2v[h] * tanh_fast(xj * W1[h] + B1[h]);
            }
            sTi[n >> 6][n & 63] = fi;
            sTj[n >> 6][n & 63] = fj;
        }
    }

    // ---- Stage A1: 12 raw weight rows {Wm,Wmax,Wmin} x {ij,ji} x {o0,o1} ----
    {
        int rij = (i * NCOL + j) * 2, rji = (j * NCOL + i) * 2;
        for (int idx = t; idx < 12 * D; idx += 384) {
            int r = idx >> 6, d = idx & 63;
            int op = 1 + (r >> 2);              // 0->Wm,1->Wmax,2->Wmin
            int sub = r & 3;                    // dir*2 + o
            int row = (sub < 2) ? rij : rji;
            int o   = sub & 1;
            sWraw[r][d] = Wops[op * SZ + (row + o) * D + d];
        }
    }

    // ---- Stage A2 (diag only): linear fold partials, 3 parts x 128 slots ----
    if (diag) {
        int slot = t & 127, part = t >> 7;             // 3 parts
        int o = slot >> 6, d = slot & 63;
        float sp = 0.f, smx = 0.f, smn = 0.f, sct = 0.f;
#pragma unroll
        for (int k = 0; k < 8; k++) {
            int j2 = part * 8 + k;
            if (j2 < NCOL) {
                int ij = ((i * NCOL + j2) * 2 + o) * D + d;
                int ji = ((j2 * NCOL + i) * 2 + o) * D + d;
                sp  += Wops[ij]          + Wops[ji];
                smx += Wops[2 * SZ + ij] + Wops[2 * SZ + ji];
                smn += Wops[3 * SZ + ij] + Wops[3 * SZ + ji];
                sct += Wcat[((i * NCOL + j2) * 2 + o) * (2 * D) + d]       // Wc1 row
                     + Wcat[((j2 * NCOL + i) * 2 + o) * (2 * D) + D + d];  // Wc2 col
            }
        }
        s_Lred[part][slot] = make_float4(sp, smx, smn, sct);
    }
    __syncthreads();

    // ---- Stage B: symmetrize weights; diag: combine L ----
    if (t < 4 * D) {
        int comp = t >> 6, d = t & 63;
        float aw1 = aw[1], aw2 = aw[2], aw3 = aw[3];
        float v;
        if (comp < 2) {          // wq for o = comp
            v = diag ? aw1 * sWraw[comp][d]
                     : aw1 * (sWraw[comp][d] + sWraw[2 + comp][d]);
        } else if (diag) {
            v = 0.f;             // wd vanishes on diagonal
        } else {
            int o = comp - 2;
            v = 0.5f * (aw2 * (sWraw[4 + o][d] + sWraw[6 + o][d])
                      - aw3 * (sWraw[8 + o][d] + sWraw[10 + o][d]));
        }
        float* f = (float*)&sW[d];
        f[comp] = v;
    }
    if (diag && t < 128) {
        float4 a = s_Lred[0][t], b = s_Lred[1][t], c = s_Lred[2][t];
        sL[t] = aw[0] * (a.x + b.x + c.x) + aw[4] * (a.w + b.w + c.w)
              + 0.5f * (aw[2] * (a.y + b.y + c.y) + aw[3] * (a.z + b.z + c.z));
    }
    __syncthreads();

    // ---- Stage C: tabulate S[p][e1][e2] ----
    if (t < NE2) {
        int e1 = t / NEMB, e2 = t % NEMB;
        bool dl = diag && (e1 == e2);
        float s0 = 0.f, s1 = 0.f, l0 = 0.f, l1 = 0.f;
#pragma unroll 4
        for (int d = 0; d < D; d++) {
            float4 w = sW[d];
            float ti = sTi[e1][d], tj = sTj[e2][d];
            float m = ti * tj;
            float a = fabsf(ti - tj);
            s0 = fmaf(w.x, m, fmaf(w.z, a, s0));
            s1 = fmaf(w.y, m, fmaf(w.w, a, s1));
            if (dl) { l0 = fmaf(ti, sL[d], l0); l1 = fmaf(ti, sL[D + d], l1); }
        }
        if (dl) { s0 += l0; s1 += l1; }
        g_S[p * NE2 + t] = make_float2(s0, s1);
    }
}

// ---------------- k_main: 256 blocks, 8 batches each, 8 gathers/lane ---------
__global__ void __launch_bounds__(256, 8)
k_main(const int* __restrict__ features, float* __restrict__ out, int out_size) {
    __shared__ int   s_feat[NCOL][8];
    __shared__ float s_red[8][8][2];
    int t = threadIdx.x;
    int b0 = blockIdx.x * 8;

    for (int idx = t; idx < NCOL * 8; idx += 256)
        s_feat[idx >> 3][idx & 7] = features[(idx >> 3) * B + b0 + (idx & 7)];
    __syncthreads();

    int w = t >> 5, l = t & 31;
    int bl = l & 7, s = l >> 3;        // 4 subchunks of 8 pairs
    int pc = w * 32 + s * 8;
    int i, j; pair_ij(pc, i, j);

    float a0 = 0.f, a1 = 0.f;
#pragma unroll
    for (int k = 0; k < 8; k++) {
        int p = pc + k;
        if (p < NPAIR) {
            int e1 = s_feat[i][bl], e2 = s_feat[j][bl];
            float2 v = __ldg(&g_S[p * NE2 + e1 * NEMB + e2]);
            a0 += v.x; a1 += v.y;
            j++; if (j == NCOL) { i++; j = i; }
        }
    }
    a0 += __shfl_xor_sync(0xffffffffu, a0, 8);
    a1 += __shfl_xor_sync(0xffffffffu, a1, 8);
    a0 += __shfl_xor_sync(0xffffffffu, a0, 16);
    a1 += __shfl_xor_sync(0xffffffffu, a1, 16);
    if (s == 0) { s_red[w][bl][0] = a0; s_red[w][bl][1] = a1; }
    __syncthreads();
    if (t < 8) {
        float r0 = 0.f, r1 = 0.f;
#pragma unroll
        for (int ww = 0; ww < 8; ww++) { r0 += s_red[ww][t][0]; r1 += s_red[ww][t][1]; }
        int b = b0 + t;
        out[b * 2] = r0; out[b * 2 + 1] = r1;
    }

    // regularizer scalar (colsq ready from k_S)
    if (blockIdx.x == 0 && t >= 32 && t < 64 && out_size > 2 * B) {
        int ll = t - 32;
        float v = (ll < NCOL) ? sqrtf(g_colsq[ll]) : 0.f;
#pragma unroll
        for (int o = 16; o; o >>= 1) v += __shfl_xor_sync(0xffffffffu, v, o);
        if (ll == 0) out[2 * B] = 0.001f * (2.0f * NCOL) * v;
    }
}

// ---------------- launch -----------------------------------------------------
extern "C" void kernel_launch(void* const* d_in, const int* in_sizes, int n_in,
                              void* d_out, int out_size) {
    const int*   features = (const int*)  d_in[0];
    const float* tables   = (const float*)d_in[1];
    const float* w1       = (const float*)d_in[2];
    const float* b1       = (const float*)d_in[3];
    const float* w2       = (const float*)d_in[4];
    const float* b2       = (const float*)d_in[5];
    const float* Wops     = (const float*)d_in[6];
    const float* Wcat     = (const float*)d_in[7];
    const float* aw       = (const float*)d_in[8];
    float* out = (float*)d_out;

    k_S    <<<NPAIR + NCOL, 384>>>(tables, w1, b1, w2, b2, Wops, Wcat, aw, features);
    k_main <<<B / 8, 256>>>(features, out, out_size);
}